// round 7
// baseline (speedup 1.0000x reference)
#include <cuda_runtime.h>
#include <cuda_fp16.h>
#include <cstdint>
#include <math.h>

#define NTHREADS 256
#define TMC      64
#define NCHUNK   16          // 256 k / 16
#define KCH      16
#define A_MAT    3072        // 64 rows * 48B
#define B_MAT    12288       // 256 rows * 48B
#define A_STRIDE 48
#define B_STRIDE 48

#define OFF_A    0                           // [2 stage][2 mat(hi,lo)] * A_MAT = 12288
#define OFF_B    12288                       // [3 stage][2 mat(hi,lo)] * B_MAT = 73728
#define OFF_W1S  86016
#define OFF_B1S  89088
#define OFF_B2S  90112
#define OFF_W3S  91136
#define OFF_B3S  94208
#define OFF_RS   94224
#define OFF_XS   94992
#define SMEM_BYTES 97296                     // *2 = 194.6KB <= 228KB -> 2 CTA/SM
#define OFF_PSUM OFF_A                       // reuse A region post-mainloop

// ---------------- global scratch: W2^T split fp16 hi/lo, [n][k] 512B rows ----
__device__ __align__(128) __half g_w2t_hi[256 * 256];
__device__ __align__(128) __half g_w2t_lo[256 * 256];

__device__ __forceinline__ uint32_t smem_u32(const void* p) {
    uint32_t a;
    asm("{ .reg .u64 t; cvta.to.shared.u64 t, %1; cvt.u32.u64 %0, t; }" : "=r"(a) : "l"(p));
    return a;
}

#define LDSM4(r, a)                                                           \
    asm volatile("ldmatrix.sync.aligned.m8n8.x4.shared.b16 {%0,%1,%2,%3}, [%4];" \
        : "=r"((r)[0]), "=r"((r)[1]), "=r"((r)[2]), "=r"((r)[3]) : "r"(a))

#define MMA_F16(acc, A, b0, b1)                                               \
    asm volatile(                                                             \
        "mma.sync.aligned.m16n8k16.row.col.f32.f16.f16.f32 "                  \
        "{%0,%1,%2,%3}, {%4,%5,%6,%7}, {%8,%9}, {%0,%1,%2,%3};"               \
        : "+f"((acc)[0]), "+f"((acc)[1]), "+f"((acc)[2]), "+f"((acc)[3])      \
        : "r"((A)[0]), "r"((A)[1]), "r"((A)[2]), "r"((A)[3]),                 \
          "r"(b0), "r"(b1))

#define CP_ASYNC16(dst, src)                                                  \
    asm volatile("cp.async.cg.shared.global [%0], [%1], 16;" :: "r"(dst), "l"(src) : "memory")
#define CP_COMMIT()  asm volatile("cp.async.commit_group;" ::: "memory")
#define CP_WAIT1()   asm volatile("cp.async.wait_group 1;" ::: "memory")

// ---------------- kernel 1: transpose + split W2 -> fp16 hi/lo [n][k] -------
__global__ void prep_w2(const float* __restrict__ W2) {
    __shared__ float tile[32][33];
    int bx = blockIdx.x & 7;        // n tile
    int by = blockIdx.x >> 3;       // k tile
    int tx = threadIdx.x & 31;
    int ty = threadIdx.x >> 5;
    #pragma unroll
    for (int i = 0; i < 32; i += 8)
        tile[ty + i][tx] = W2[(by * 32 + ty + i) * 256 + bx * 32 + tx];
    __syncthreads();
    #pragma unroll
    for (int i = 0; i < 32; i += 8) {
        int n = bx * 32 + ty + i;
        int k = by * 32 + tx;
        float v = tile[tx][ty + i];                 // W2[k][n]
        __half h = __float2half_rn(v);
        g_w2t_hi[n * 256 + k] = h;
        g_w2t_lo[n * 256 + k] = __float2half_rn(v - __half2float(h));
    }
}

// ---------------- kernel 2: fused main ----------------
__global__ __launch_bounds__(NTHREADS, 2)
void nn_adiab_mma(const float* __restrict__ x,
                  const float* __restrict__ W1,
                  const float* __restrict__ b1,
                  const float* __restrict__ b2,
                  const float* __restrict__ W3,
                  const float* __restrict__ b3,
                  float* __restrict__ out,
                  int B)
{
    extern __shared__ __align__(128) char smem[];
    const uint32_t sb = smem_u32(smem);
    const int tid  = threadIdx.x;
    const int wid  = tid >> 5;
    const int lane = tid & 31;
    const int g    = lane >> 2;
    const int t    = lane & 3;
    const int wy   = wid & 1;        // m warp coord (2 x 32 rows)
    const int wx   = wid >> 1;       // n warp coord (4 x 64 cols)
    const int m0w  = wy * 32;
    const int n0w  = wx * 64;
    const int row0 = blockIdx.x * TMC;

    const char* ghi = (const char*)g_w2t_hi;
    const char* glo = (const char*)g_w2t_lo;

    // ---- issue cp.async for B chunks 0,1 immediately (stages 0,1) ----
    #pragma unroll
    for (int ci = 0; ci < 2; ci++) {
        #pragma unroll
        for (int u = 0; u < 4; u++) {
            int gi  = u * NTHREADS + tid;    // 0..1023
            int mat = gi >> 9;
            int wi  = gi & 511;
            int n   = wi >> 1;
            int seg = wi & 1;
            uint32_t dst = sb + OFF_B + (ci * 2 + mat) * B_MAT + n * B_STRIDE + seg * 16;
            CP_ASYNC16(dst, (mat ? glo : ghi) + n * 512 + ci * 32 + seg * 16);
        }
        CP_COMMIT();
    }

    float* w1s = (float*)(smem + OFF_W1S);
    float* b1s = (float*)(smem + OFF_B1S);
    float* b2s = (float*)(smem + OFF_B2S);
    float* w3s = (float*)(smem + OFF_W3S);
    float* b3s = (float*)(smem + OFF_B3S);
    float* rs  = (float*)(smem + OFF_RS);
    float* xs  = (float*)(smem + OFF_XS);

    for (int i = tid; i < 768; i += NTHREADS) w1s[i] = W1[i];
    for (int i = tid; i < 256; i += NTHREADS) { b1s[i] = b1[i]; b2s[i] = b2[i]; }
    for (int i = tid; i < 768; i += NTHREADS) w3s[i] = W3[i];
    if (tid < 3) b3s[tid] = b3[tid];
    for (int i = tid; i < TMC * 9; i += NTHREADS) {
        int r = row0 + i / 9;
        xs[i] = (r < B) ? x[(size_t)row0 * 9 + i] : 0.f;
    }
    __syncthreads();

    // ---- pairwise distances ----
    if (tid < TMC) {
        const float* p = xs + tid * 9;
        float ax=p[0],ay=p[1],az=p[2], bx=p[3],by=p[4],bz=p[5], cx=p[6],cy=p[7],cz=p[8];
        float d0x=ax-bx, d0y=ay-by, d0z=az-bz;
        float d1x=ax-cx, d1y=ay-cy, d1z=az-cz;
        float d2x=bx-cx, d2y=by-cy, d2z=bz-cz;
        rs[tid*3+0] = sqrtf(d0x*d0x + d0y*d0y + d0z*d0z);
        rs[tid*3+1] = sqrtf(d1x*d1x + d1y*d1y + d1z*d1z);
        rs[tid*3+2] = sqrtf(d2x*d2x + d2y*d2y + d2z*d2z);
    }
    __syncthreads();

    // ---- A chunk writer: thread handles 2 k-pairs of h1, split fp16 ----
    // chunk cc: 64 m x 8 kpairs = 512 pairs; flat = i*256+tid
    #define WRITE_A_CHUNK(cc) do {                                             \
        uint32_t abase = sb + OFF_A + (((cc) & 1) * 2) * A_MAT;                \
        _Pragma("unroll")                                                      \
        for (int i = 0; i < 2; i++) {                                          \
            int flat = i * NTHREADS + tid;                                     \
            int m  = flat >> 3;                                                \
            int kp = flat & 7;                                                 \
            int kg = (cc) * KCH + kp * 2;                                      \
            float r0 = rs[m*3+0], r1 = rs[m*3+1], r2 = rs[m*3+2];              \
            float v0 = fmaf(r0, w1s[kg],   fmaf(r1, w1s[256+kg],   fmaf(r2, w1s[512+kg],   b1s[kg])));   \
            float v1 = fmaf(r0, w1s[kg+1], fmaf(r1, w1s[256+kg+1], fmaf(r2, w1s[512+kg+1], b1s[kg+1]))); \
            v0 = fmaxf(v0, 0.f); v1 = fmaxf(v1, 0.f);                          \
            __half2 hp = __floats2half2_rn(v0, v1);                            \
            float h0f = __half2float(__low2half(hp));                          \
            float h1f = __half2float(__high2half(hp));                         \
            __half2 lp = __floats2half2_rn(v0 - h0f, v1 - h1f);                \
            uint32_t off = (uint32_t)m * A_STRIDE + (uint32_t)kp * 4;          \
            *(uint32_t*)(smem + (abase - sb) + off)         = *(uint32_t*)&hp; \
            *(uint32_t*)(smem + (abase - sb) + A_MAT + off) = *(uint32_t*)&lp; \
        }                                                                      \
    } while (0)

    WRITE_A_CHUNK(0);

    // ---- per-thread ldmatrix offsets ----
    const int jj = lane >> 3, rr = lane & 7;
    const int mOff  = ((jj & 1) << 3) + rr;          // A row within warp m-tile
    const int kOffA = ((jj >> 1) << 3) * 2;          // 0 or 16 bytes
    const uint32_t aoff0 = (uint32_t)(m0w + mOff) * A_STRIDE + kOffA;          // mt=0
    const int nOffB = ((jj >> 1) << 3) + rr;
    const int kOffB = ((jj & 1) << 3) * 2;           // 0 or 16 bytes
    const uint32_t boff  = (uint32_t)(n0w + nOffB) * B_STRIDE + kOffB;

    // ---- accumulators ----
    float acc[2][8][4];
    #pragma unroll
    for (int mt = 0; mt < 2; mt++)
        #pragma unroll
        for (int nt = 0; nt < 8; nt++)
            #pragma unroll
            for (int q = 0; q < 4; q++) acc[mt][nt][q] = 0.f;

    // ---- mainloop: 16 chunks, 3-stage B, 2-stage A, 1 sync/chunk ----
    for (int c = 0; c < NCHUNK; c++) {
        CP_WAIT1();               // own B(c) transfers done (<=1 group pending)
        __syncthreads();          // B(c),A(c) visible; B(c-1)/A(c-1) reads retired

        if (c + 2 < NCHUNK) {     // refill stage (c+2)%3 (held B(c-1), now free)
            int st = (c + 2) % 3;
            #pragma unroll
            for (int u = 0; u < 4; u++) {
                int gi  = u * NTHREADS + tid;
                int mat = gi >> 9;
                int wi  = gi & 511;
                int n   = wi >> 1;
                int seg = wi & 1;
                uint32_t dst = sb + OFF_B + (st * 2 + mat) * B_MAT + n * B_STRIDE + seg * 16;
                CP_ASYNC16(dst, (mat ? glo : ghi) + n * 512 + (c + 2) * 32 + seg * 16);
            }
        }
        CP_COMMIT();              // commit unconditionally to keep group counting uniform

        if (c + 1 < NCHUNK) WRITE_A_CHUNK(c + 1);

        // ---- ldsm + 3-term mma on chunk c ----
        uint32_t ah[2][4], al[2][4];
        {
            uint32_t abase = sb + OFF_A + ((c & 1) * 2) * A_MAT;
            LDSM4(ah[0], abase + aoff0);
            LDSM4(ah[1], abase + aoff0 + 16 * A_STRIDE);
            LDSM4(al[0], abase + A_MAT + aoff0);
            LDSM4(al[1], abase + A_MAT + aoff0 + 16 * A_STRIDE);
        }
        uint32_t bbase = sb + OFF_B + ((c % 3) * 2) * B_MAT + boff;
        #pragma unroll
        for (int q = 0; q < 8; q += 2) {
            uint32_t bh[4], bl[4];
            LDSM4(bh, bbase + q * (8 * B_STRIDE));
            LDSM4(bl, bbase + B_MAT + q * (8 * B_STRIDE));
            #pragma unroll
            for (int mt = 0; mt < 2; mt++) {
                MMA_F16(acc[mt][q],     ah[mt], bh[0], bh[1]);
                MMA_F16(acc[mt][q],     al[mt], bh[0], bh[1]);
                MMA_F16(acc[mt][q],     ah[mt], bl[0], bl[1]);
                MMA_F16(acc[mt][q + 1], ah[mt], bh[2], bh[3]);
                MMA_F16(acc[mt][q + 1], al[mt], bh[2], bh[3]);
                MMA_F16(acc[mt][q + 1], ah[mt], bl[2], bl[3]);
            }
        }
    }

    // ---- epilogue: bias2 + relu + layer3 partials ----
    __syncthreads();                          // retire all mainloop reads
    float* psum = (float*)(smem + OFF_PSUM);  // [4 wx][64 row][3]
    #pragma unroll
    for (int mt = 0; mt < 2; mt++) {
        float p[2][3];
        p[0][0]=p[0][1]=p[0][2]=0.f;
        p[1][0]=p[1][1]=p[1][2]=0.f;
        #pragma unroll
        for (int nt = 0; nt < 8; nt++) {
            int n  = n0w + nt * 8 + 2 * t;
            int n2 = n + 1;
            float bn = b2s[n], bn2 = b2s[n2];
            float h00 = fmaxf(acc[mt][nt][0] + bn,  0.f);
            float h01 = fmaxf(acc[mt][nt][1] + bn2, 0.f);
            float h10 = fmaxf(acc[mt][nt][2] + bn,  0.f);
            float h11 = fmaxf(acc[mt][nt][3] + bn2, 0.f);
            #pragma unroll
            for (int j = 0; j < 3; j++) {
                float wA = w3s[n * 3 + j], wB = w3s[n2 * 3 + j];
                p[0][j] = fmaf(h00, wA, fmaf(h01, wB, p[0][j]));
                p[1][j] = fmaf(h10, wA, fmaf(h11, wB, p[1][j]));
            }
        }
        #pragma unroll
        for (int s = 0; s < 2; s++)
            #pragma unroll
            for (int j = 0; j < 3; j++) {
                p[s][j] += __shfl_xor_sync(0xffffffffu, p[s][j], 1);
                p[s][j] += __shfl_xor_sync(0xffffffffu, p[s][j], 2);
            }
        if (t == 0) {
            #pragma unroll
            for (int s = 0; s < 2; s++) {
                int rloc = m0w + mt * 16 + g + 8 * s;
                #pragma unroll
                for (int j = 0; j < 3; j++)
                    psum[(wx * TMC + rloc) * 3 + j] = p[s][j];
            }
        }
    }
    __syncthreads();

    // ---- final cross-warp reduce + eigen + store ----
    if (tid < TMC) {
        int gr = row0 + tid;
        if (gr < B) {
            float w0 = b3s[0], w1 = b3s[1], w2 = b3s[2];
            #pragma unroll
            for (int q = 0; q < 4; q++) {
                w0 += psum[(q * TMC + tid) * 3 + 0];
                w1 += psum[(q * TMC + tid) * 3 + 1];
                w2 += psum[(q * TMC + tid) * 3 + 2];
            }
            float mean = 0.5f * (w0 + w1);
            float dd   = 0.5f * (w0 - w1);
            float rad  = sqrtf(dd * dd + w2 * w2);
            out[(size_t)gr * 2 + 0] = mean - rad;
            out[(size_t)gr * 2 + 1] = mean + rad;
        }
    }
}

extern "C" void kernel_launch(void* const* d_in, const int* in_sizes, int n_in,
                              void* d_out, int out_size)
{
    const float* x  = (const float*)d_in[0];
    const float* W1 = (const float*)d_in[1];
    const float* b1 = (const float*)d_in[2];
    const float* W2 = (const float*)d_in[3];
    const float* b2 = (const float*)d_in[4];
    const float* W3 = (const float*)d_in[5];
    const float* b3 = (const float*)d_in[6];
    float* out = (float*)d_out;

    int B = in_sizes[0] / 9;
    int grid = (B + TMC - 1) / TMC;

    prep_w2<<<64, 256>>>(W2);

    cudaFuncSetAttribute(nn_adiab_mma,
                         cudaFuncAttributeMaxDynamicSharedMemorySize, SMEM_BYTES);
    nn_adiab_mma<<<grid, NTHREADS, SMEM_BYTES>>>(x, W1, b1, b2, W3, b3, out, B);
}

// round 8
// speedup vs baseline: 1.0011x; 1.0011x over previous
#include <cuda_runtime.h>
#include <cuda_fp16.h>
#include <cstdint>
#include <math.h>

#define NTHREADS 256
#define TMC      64
#define NCHUNK   16          // 256 k / 16
#define KCH      16
#define A_MAT    3072        // 64 rows * 48B
#define B_MAT    12288       // 256 rows * 48B
#define A_STRIDE 48
#define B_STRIDE 48

#define OFF_A    0                           // [2 stage][2 mat(hi,lo)] * A_MAT = 12288
#define OFF_B    12288                       // [3 stage][2 mat(hi,lo)] * B_MAT = 73728
#define OFF_W1S  86016
#define OFF_B1S  89088
#define OFF_B2S  90112
#define OFF_W3S  91136
#define OFF_B3S  94208
#define OFF_RS   94224
#define OFF_XS   94992
#define SMEM_BYTES 97296                     // *2 = 194.6KB <= 228KB -> 2 CTA/SM
#define OFF_PSUM OFF_A                       // reuse A region post-mainloop

// ---------------- global scratch: W2^T split fp16 hi/lo, [n][k] 512B rows ----
__device__ __align__(128) __half g_w2t_hi[256 * 256];
__device__ __align__(128) __half g_w2t_lo[256 * 256];

__device__ __forceinline__ uint32_t smem_u32(const void* p) {
    uint32_t a;
    asm("{ .reg .u64 t; cvta.to.shared.u64 t, %1; cvt.u32.u64 %0, t; }" : "=r"(a) : "l"(p));
    return a;
}

#define LDSM4(r, a)                                                           \
    asm volatile("ldmatrix.sync.aligned.m8n8.x4.shared.b16 {%0,%1,%2,%3}, [%4];" \
        : "=r"((r)[0]), "=r"((r)[1]), "=r"((r)[2]), "=r"((r)[3]) : "r"(a))

#define MMA_F16(acc, A, b0, b1)                                               \
    asm volatile(                                                             \
        "mma.sync.aligned.m16n8k16.row.col.f32.f16.f16.f32 "                  \
        "{%0,%1,%2,%3}, {%4,%5,%6,%7}, {%8,%9}, {%0,%1,%2,%3};"               \
        : "+f"((acc)[0]), "+f"((acc)[1]), "+f"((acc)[2]), "+f"((acc)[3])      \
        : "r"((A)[0]), "r"((A)[1]), "r"((A)[2]), "r"((A)[3]),                 \
          "r"(b0), "r"(b1))

#define CP_ASYNC16(dst, src)                                                  \
    asm volatile("cp.async.cg.shared.global [%0], [%1], 16;" :: "r"(dst), "l"(src) : "memory")
#define CP_COMMIT()  asm volatile("cp.async.commit_group;" ::: "memory")
#define CP_WAIT1()   asm volatile("cp.async.wait_group 1;" ::: "memory")

// ---------------- kernel 1: transpose + split W2 -> fp16 hi/lo [n][k] -------
__global__ void prep_w2(const float* __restrict__ W2) {
    __shared__ float tile[32][33];
    int bx = blockIdx.x & 7;        // n tile
    int by = blockIdx.x >> 3;       // k tile
    int tx = threadIdx.x & 31;
    int ty = threadIdx.x >> 5;
    #pragma unroll
    for (int i = 0; i < 32; i += 8)
        tile[ty + i][tx] = W2[(by * 32 + ty + i) * 256 + bx * 32 + tx];
    __syncthreads();
    #pragma unroll
    for (int i = 0; i < 32; i += 8) {
        int n = bx * 32 + ty + i;
        int k = by * 32 + tx;
        float v = tile[tx][ty + i];                 // W2[k][n]
        __half h = __float2half_rn(v);
        g_w2t_hi[n * 256 + k] = h;
        g_w2t_lo[n * 256 + k] = __float2half_rn(v - __half2float(h));
    }
}

// ---------------- kernel 2: fused main ----------------
__global__ __launch_bounds__(NTHREADS, 2)
void nn_adiab_mma(const float* __restrict__ x,
                  const float* __restrict__ W1,
                  const float* __restrict__ b1,
                  const float* __restrict__ b2,
                  const float* __restrict__ W3,
                  const float* __restrict__ b3,
                  float* __restrict__ out,
                  int B)
{
    extern __shared__ __align__(128) char smem[];
    const uint32_t sb = smem_u32(smem);
    const int tid  = threadIdx.x;
    const int wid  = tid >> 5;
    const int lane = tid & 31;
    const int g    = lane >> 2;
    const int t    = lane & 3;
    const int wy   = wid & 1;        // m warp coord (2 x 32 rows)
    const int wx   = wid >> 1;       // n warp coord (4 x 64 cols)
    const int m0w  = wy * 32;
    const int n0w  = wx * 64;
    const int row0 = blockIdx.x * TMC;

    const char* ghi = (const char*)g_w2t_hi;
    const char* glo = (const char*)g_w2t_lo;

    // ---- issue cp.async for B chunks 0,1 immediately (stages 0,1) ----
    #pragma unroll
    for (int ci = 0; ci < 2; ci++) {
        #pragma unroll
        for (int u = 0; u < 4; u++) {
            int gi  = u * NTHREADS + tid;    // 0..1023
            int mat = gi >> 9;
            int wi  = gi & 511;
            int n   = wi >> 1;
            int seg = wi & 1;
            uint32_t dst = sb + OFF_B + (ci * 2 + mat) * B_MAT + n * B_STRIDE + seg * 16;
            CP_ASYNC16(dst, (mat ? glo : ghi) + n * 512 + ci * 32 + seg * 16);
        }
        CP_COMMIT();
    }

    float* w1s = (float*)(smem + OFF_W1S);
    float* b1s = (float*)(smem + OFF_B1S);
    float* b2s = (float*)(smem + OFF_B2S);
    float* w3s = (float*)(smem + OFF_W3S);
    float* b3s = (float*)(smem + OFF_B3S);
    float* rs  = (float*)(smem + OFF_RS);
    float* xs  = (float*)(smem + OFF_XS);

    for (int i = tid; i < 768; i += NTHREADS) w1s[i] = W1[i];
    for (int i = tid; i < 256; i += NTHREADS) { b1s[i] = b1[i]; b2s[i] = b2[i]; }
    for (int i = tid; i < 768; i += NTHREADS) w3s[i] = W3[i];
    if (tid < 3) b3s[tid] = b3[tid];
    for (int i = tid; i < TMC * 9; i += NTHREADS) {
        int r = row0 + i / 9;
        xs[i] = (r < B) ? x[(size_t)row0 * 9 + i] : 0.f;
    }
    __syncthreads();

    // ---- pairwise distances ----
    if (tid < TMC) {
        const float* p = xs + tid * 9;
        float ax=p[0],ay=p[1],az=p[2], bx=p[3],by=p[4],bz=p[5], cx=p[6],cy=p[7],cz=p[8];
        float d0x=ax-bx, d0y=ay-by, d0z=az-bz;
        float d1x=ax-cx, d1y=ay-cy, d1z=az-cz;
        float d2x=bx-cx, d2y=by-cy, d2z=bz-cz;
        rs[tid*3+0] = sqrtf(d0x*d0x + d0y*d0y + d0z*d0z);
        rs[tid*3+1] = sqrtf(d1x*d1x + d1y*d1y + d1z*d1z);
        rs[tid*3+2] = sqrtf(d2x*d2x + d2y*d2y + d2z*d2z);
    }
    __syncthreads();

    // ---- A chunk writer: thread handles 2 k-pairs of h1, split fp16 ----
    #define WRITE_A_CHUNK(cc) do {                                             \
        uint32_t abase = sb + OFF_A + (((cc) & 1) * 2) * A_MAT;                \
        _Pragma("unroll")                                                      \
        for (int i = 0; i < 2; i++) {                                          \
            int flat = i * NTHREADS + tid;                                     \
            int m  = flat >> 3;                                                \
            int kp = flat & 7;                                                 \
            int kg = (cc) * KCH + kp * 2;                                      \
            float r0 = rs[m*3+0], r1 = rs[m*3+1], r2 = rs[m*3+2];              \
            float v0 = fmaf(r0, w1s[kg],   fmaf(r1, w1s[256+kg],   fmaf(r2, w1s[512+kg],   b1s[kg])));   \
            float v1 = fmaf(r0, w1s[kg+1], fmaf(r1, w1s[256+kg+1], fmaf(r2, w1s[512+kg+1], b1s[kg+1]))); \
            v0 = fmaxf(v0, 0.f); v1 = fmaxf(v1, 0.f);                          \
            __half2 hp = __floats2half2_rn(v0, v1);                            \
            float h0f = __half2float(__low2half(hp));                          \
            float h1f = __half2float(__high2half(hp));                         \
            __half2 lp = __floats2half2_rn(v0 - h0f, v1 - h1f);                \
            uint32_t off = (uint32_t)m * A_STRIDE + (uint32_t)kp * 4;          \
            *(uint32_t*)(smem + (abase - sb) + off)         = *(uint32_t*)&hp; \
            *(uint32_t*)(smem + (abase - sb) + A_MAT + off) = *(uint32_t*)&lp; \
        }                                                                      \
    } while (0)

    WRITE_A_CHUNK(0);

    // ---- per-thread ldmatrix offsets ----
    const int jj = lane >> 3, rr = lane & 7;
    const int mOff  = ((jj & 1) << 3) + rr;
    const int kOffA = ((jj >> 1) << 3) * 2;
    const uint32_t aoff0 = (uint32_t)(m0w + mOff) * A_STRIDE + kOffA;
    const int nOffB = ((jj >> 1) << 3) + rr;
    const int kOffB = ((jj & 1) << 3) * 2;
    const uint32_t boff  = (uint32_t)(n0w + nOffB) * B_STRIDE + kOffB;

    // ---- accumulators ----
    float acc[2][8][4];
    #pragma unroll
    for (int mt = 0; mt < 2; mt++)
        #pragma unroll
        for (int nt = 0; nt < 8; nt++)
            #pragma unroll
            for (int q = 0; q < 4; q++) acc[mt][nt][q] = 0.f;

    // ---- mainloop: 16 chunks, 3-stage B, 2-stage A, 1 sync/chunk ----
    for (int c = 0; c < NCHUNK; c++) {
        CP_WAIT1();
        __syncthreads();

        if (c + 2 < NCHUNK) {
            int st = (c + 2) % 3;
            #pragma unroll
            for (int u = 0; u < 4; u++) {
                int gi  = u * NTHREADS + tid;
                int mat = gi >> 9;
                int wi  = gi & 511;
                int n   = wi >> 1;
                int seg = wi & 1;
                uint32_t dst = sb + OFF_B + (st * 2 + mat) * B_MAT + n * B_STRIDE + seg * 16;
                CP_ASYNC16(dst, (mat ? glo : ghi) + n * 512 + (c + 2) * 32 + seg * 16);
            }
        }
        CP_COMMIT();

        if (c + 1 < NCHUNK) WRITE_A_CHUNK(c + 1);

        // ---- ldsm A ----
        uint32_t ah[2][4], al[2][4];
        {
            uint32_t abase = sb + OFF_A + ((c & 1) * 2) * A_MAT;
            LDSM4(ah[0], abase + aoff0);
            LDSM4(ah[1], abase + aoff0 + 16 * A_STRIDE);
            LDSM4(al[0], abase + A_MAT + aoff0);
            LDSM4(al[1], abase + A_MAT + aoff0 + 16 * A_STRIDE);
        }
        // ---- MMAs reordered term-major: same-acc reuse distance = 8 ----
        uint32_t bbase = sb + OFF_B + ((c % 3) * 2) * B_MAT + boff;
        #pragma unroll
        for (int h = 0; h < 2; h++) {
            uint32_t bh[8], bl[8];
            LDSM4(bh,     bbase + (h * 4 + 0) * (8 * B_STRIDE));
            LDSM4(bh + 4, bbase + (h * 4 + 2) * (8 * B_STRIDE));
            LDSM4(bl,     bbase + B_MAT + (h * 4 + 0) * (8 * B_STRIDE));
            LDSM4(bl + 4, bbase + B_MAT + (h * 4 + 2) * (8 * B_STRIDE));
            // term 1: ah * bh  (8 independent accs)
            #pragma unroll
            for (int mt = 0; mt < 2; mt++)
                #pragma unroll
                for (int q = 0; q < 4; q++)
                    MMA_F16(acc[mt][h * 4 + q], ah[mt], bh[2 * q], bh[2 * q + 1]);
            // term 2: al * bh
            #pragma unroll
            for (int mt = 0; mt < 2; mt++)
                #pragma unroll
                for (int q = 0; q < 4; q++)
                    MMA_F16(acc[mt][h * 4 + q], al[mt], bh[2 * q], bh[2 * q + 1]);
            // term 3: ah * bl
            #pragma unroll
            for (int mt = 0; mt < 2; mt++)
                #pragma unroll
                for (int q = 0; q < 4; q++)
                    MMA_F16(acc[mt][h * 4 + q], ah[mt], bl[2 * q], bl[2 * q + 1]);
        }
    }

    // ---- epilogue: bias2 + relu + layer3 partials ----
    __syncthreads();
    float* psum = (float*)(smem + OFF_PSUM);  // [4 wx][64 row][3]
    #pragma unroll
    for (int mt = 0; mt < 2; mt++) {
        float p[2][3];
        p[0][0]=p[0][1]=p[0][2]=0.f;
        p[1][0]=p[1][1]=p[1][2]=0.f;
        #pragma unroll
        for (int nt = 0; nt < 8; nt++) {
            int n  = n0w + nt * 8 + 2 * t;
            int n2 = n + 1;
            float bn = b2s[n], bn2 = b2s[n2];
            float h00 = fmaxf(acc[mt][nt][0] + bn,  0.f);
            float h01 = fmaxf(acc[mt][nt][1] + bn2, 0.f);
            float h10 = fmaxf(acc[mt][nt][2] + bn,  0.f);
            float h11 = fmaxf(acc[mt][nt][3] + bn2, 0.f);
            #pragma unroll
            for (int j = 0; j < 3; j++) {
                float wA = w3s[n * 3 + j], wB = w3s[n2 * 3 + j];
                p[0][j] = fmaf(h00, wA, fmaf(h01, wB, p[0][j]));
                p[1][j] = fmaf(h10, wA, fmaf(h11, wB, p[1][j]));
            }
        }
        #pragma unroll
        for (int s = 0; s < 2; s++)
            #pragma unroll
            for (int j = 0; j < 3; j++) {
                p[s][j] += __shfl_xor_sync(0xffffffffu, p[s][j], 1);
                p[s][j] += __shfl_xor_sync(0xffffffffu, p[s][j], 2);
            }
        if (t == 0) {
            #pragma unroll
            for (int s = 0; s < 2; s++) {
                int rloc = m0w + mt * 16 + g + 8 * s;
                #pragma unroll
                for (int j = 0; j < 3; j++)
                    psum[(wx * TMC + rloc) * 3 + j] = p[s][j];
            }
        }
    }
    __syncthreads();

    // ---- final cross-warp reduce + eigen + store ----
    if (tid < TMC) {
        int gr = row0 + tid;
        if (gr < B) {
            float w0 = b3s[0], w1 = b3s[1], w2 = b3s[2];
            #pragma unroll
            for (int q = 0; q < 4; q++) {
                w0 += psum[(q * TMC + tid) * 3 + 0];
                w1 += psum[(q * TMC + tid) * 3 + 1];
                w2 += psum[(q * TMC + tid) * 3 + 2];
            }
            float mean = 0.5f * (w0 + w1);
            float dd   = 0.5f * (w0 - w1);
            float rad  = sqrtf(dd * dd + w2 * w2);
            out[(size_t)gr * 2 + 0] = mean - rad;
            out[(size_t)gr * 2 + 1] = mean + rad;
        }
    }
}

extern "C" void kernel_launch(void* const* d_in, const int* in_sizes, int n_in,
                              void* d_out, int out_size)
{
    const float* x  = (const float*)d_in[0];
    const float* W1 = (const float*)d_in[1];
    const float* b1 = (const float*)d_in[2];
    const float* W2 = (const float*)d_in[3];
    const float* b2 = (const float*)d_in[4];
    const float* W3 = (const float*)d_in[5];
    const float* b3 = (const float*)d_in[6];
    float* out = (float*)d_out;

    int B = in_sizes[0] / 9;
    int grid = (B + TMC - 1) / TMC;

    prep_w2<<<64, 256>>>(W2);

    cudaFuncSetAttribute(nn_adiab_mma,
                         cudaFuncAttributeMaxDynamicSharedMemorySize, SMEM_BYTES);
    nn_adiab_mma<<<grid, NTHREADS, SMEM_BYTES>>>(x, W1, b1, b2, W3, b3, out, B);
}

// round 9
// speedup vs baseline: 1.2140x; 1.2126x over previous
#include <cuda_runtime.h>
#include <cuda_fp16.h>
#include <cstdint>
#include <math.h>

#define NTHREADS 512
#define TM       128
#define NCHUNK   8           // 256 k / 32
#define KCH      32
#define A_STRIDE 528         // 512 + 16 pad -> ldmatrix conflict-free
#define B_STRIDE 80          // 64 + 16 pad  -> ldmatrix conflict-free
#define A_MAT    (TM * A_STRIDE)      // 67584
#define B_MAT    (256 * B_STRIDE)     // 20480

#define OFF_AHI  0
#define OFF_ALO  A_MAT                        // 67584
#define OFF_B0   (2 * A_MAT)                  // 135168  [2 buf][2 mat] * B_MAT
#define OFF_B2S  (OFF_B0 + 4 * B_MAT)         // 217088
#define OFF_W3S  (OFF_B2S + 1024)             // 218112
#define OFF_B3S  (OFF_W3S + 3072)             // 221184
#define OFF_RS   (OFF_B3S + 16)               // 221200
#define SMEM_BYTES (OFF_RS + 1536)            // 222736 (<= 227KB, 1 CTA/SM)
// transient regions (inside B buf1, free until chunk 1 is issued):
#define OFF_W1T  (OFF_B0 + 2 * B_MAT)         // 176128
#define OFF_B1T  (OFF_W1T + 3072)
#define OFF_XS   (OFF_B1T + 1024)
// epilogue psum reuses B buf0 region:
#define OFF_PSUM OFF_B0

// ---------------- global scratch: W2^T split fp16 hi/lo, [n][k] 512B rows ----
__device__ __align__(128) __half g_w2t_hi[256 * 256];
__device__ __align__(128) __half g_w2t_lo[256 * 256];

__device__ __forceinline__ uint32_t smem_u32(const void* p) {
    uint32_t a;
    asm("{ .reg .u64 t; cvta.to.shared.u64 t, %1; cvt.u32.u64 %0, t; }" : "=r"(a) : "l"(p));
    return a;
}

#define LDSM4(r, a)                                                           \
    asm volatile("ldmatrix.sync.aligned.m8n8.x4.shared.b16 {%0,%1,%2,%3}, [%4];" \
        : "=r"((r)[0]), "=r"((r)[1]), "=r"((r)[2]), "=r"((r)[3]) : "r"(a))

#define MMA_F16(acc, A, b0, b1)                                               \
    asm volatile(                                                             \
        "mma.sync.aligned.m16n8k16.row.col.f32.f16.f16.f32 "                  \
        "{%0,%1,%2,%3}, {%4,%5,%6,%7}, {%8,%9}, {%0,%1,%2,%3};"               \
        : "+f"((acc)[0]), "+f"((acc)[1]), "+f"((acc)[2]), "+f"((acc)[3])      \
        : "r"((A)[0]), "r"((A)[1]), "r"((A)[2]), "r"((A)[3]),                 \
          "r"(b0), "r"(b1))

#define CP_ASYNC16(dst, src)                                                  \
    asm volatile("cp.async.cg.shared.global [%0], [%1], 16;" :: "r"(dst), "l"(src) : "memory")
#define CP_COMMIT()  asm volatile("cp.async.commit_group;" ::: "memory")
#define CP_WAIT0()   asm volatile("cp.async.wait_group 0;" ::: "memory")

// ---------------- kernel 1: transpose + split W2 -> fp16 hi/lo [n][k] -------
__global__ void prep_w2(const float* __restrict__ W2) {
    __shared__ float tile[32][33];
    int bx = blockIdx.x & 7;        // n tile
    int by = blockIdx.x >> 3;       // k tile
    int tx = threadIdx.x & 31;
    int ty = threadIdx.x >> 5;
    #pragma unroll
    for (int i = 0; i < 32; i += 8)
        tile[ty + i][tx] = W2[(by * 32 + ty + i) * 256 + bx * 32 + tx];
    __syncthreads();
    #pragma unroll
    for (int i = 0; i < 32; i += 8) {
        int n = bx * 32 + ty + i;
        int k = by * 32 + tx;
        float v = tile[tx][ty + i];                 // W2[k][n]
        __half h = __float2half_rn(v);
        g_w2t_hi[n * 256 + k] = h;
        g_w2t_lo[n * 256 + k] = __float2half_rn(v - __half2float(h));
    }
}

// issue one B chunk (32 k-cols of hi+lo) into buffer `buf`
__device__ __forceinline__ void issue_b_chunk(uint32_t sb, const char* ghi,
                                              const char* glo, int c, int buf, int tid)
{
    #pragma unroll
    for (int u = 0; u < 4; u++) {
        int gi  = u * NTHREADS + tid;     // 0..2047
        int mat = gi >> 10;
        int wi  = gi & 1023;
        int n   = wi >> 2;
        int seg = wi & 3;
        uint32_t dst = sb + OFF_B0 + (buf * 2 + mat) * B_MAT + n * B_STRIDE + seg * 16;
        CP_ASYNC16(dst, (mat ? glo : ghi) + n * 512 + c * 64 + seg * 16);
    }
    CP_COMMIT();
}

// ---------------- kernel 2: fused main ----------------
__global__ __launch_bounds__(NTHREADS, 1)
void nn_adiab_mma(const float* __restrict__ x,
                  const float* __restrict__ W1,
                  const float* __restrict__ b1,
                  const float* __restrict__ b2,
                  const float* __restrict__ W3,
                  const float* __restrict__ b3,
                  float* __restrict__ out,
                  int B)
{
    extern __shared__ __align__(128) char smem[];
    const uint32_t sb = smem_u32(smem);
    const int tid  = threadIdx.x;
    const int wid  = tid >> 5;
    const int lane = tid & 31;
    const int g    = lane >> 2;
    const int t    = lane & 3;
    const int wy   = wid & 3;        // 4 m-warps x 32 rows
    const int wx   = wid >> 2;       // 4 n-warps x 64 cols
    const int m0w  = wy * 32;
    const int n0w  = wx * 64;
    const int row0 = blockIdx.x * TM;

    const char* ghi = (const char*)g_w2t_hi;
    const char* glo = (const char*)g_w2t_lo;

    // ---- prefetch B chunk 0 into buf 0 immediately ----
    issue_b_chunk(sb, ghi, glo, 0, 0, tid);

    // ---- transient loads (live in B buf1 region until chunk 1 issued) ----
    float* w1s = (float*)(smem + OFF_W1T);
    float* b1s = (float*)(smem + OFF_B1T);
    float* xs  = (float*)(smem + OFF_XS);
    float* b2s = (float*)(smem + OFF_B2S);
    float* w3s = (float*)(smem + OFF_W3S);
    float* b3s = (float*)(smem + OFF_B3S);
    float* rs  = (float*)(smem + OFF_RS);

    for (int i = tid; i < 768; i += NTHREADS) w1s[i] = W1[i];
    for (int i = tid; i < 256; i += NTHREADS) { b1s[i] = b1[i]; b2s[i] = b2[i]; }
    for (int i = tid; i < 768; i += NTHREADS) w3s[i] = W3[i];
    if (tid < 3) b3s[tid] = b3[tid];
    for (int i = tid; i < TM * 9; i += NTHREADS) {
        int r = row0 + i / 9;
        xs[i] = (r < B) ? x[(size_t)row0 * 9 + i] : 0.f;
    }
    __syncthreads();

    // ---- pairwise distances ----
    if (tid < TM) {
        const float* p = xs + tid * 9;
        float ax=p[0],ay=p[1],az=p[2], bx=p[3],by=p[4],bz=p[5], cx=p[6],cy=p[7],cz=p[8];
        float d0x=ax-bx, d0y=ay-by, d0z=az-bz;
        float d1x=ax-cx, d1y=ay-cy, d1z=az-cz;
        float d2x=bx-cx, d2y=by-cy, d2z=bz-cz;
        rs[tid*3+0] = sqrtf(d0x*d0x + d0y*d0y + d0z*d0z);
        rs[tid*3+1] = sqrtf(d1x*d1x + d1y*d1y + d1z*d1z);
        rs[tid*3+2] = sqrtf(d2x*d2x + d2y*d2y + d2z*d2z);
    }
    __syncthreads();

    // ---- build FULL A = split-fp16(h1): [128 m][256 k], hi/lo, ONCE ----
    // 16384 k-pairs, 32 per thread
    #pragma unroll 4
    for (int i = 0; i < 32; i++) {
        int flat = i * NTHREADS + tid;
        int m  = flat >> 7;
        int kp = flat & 127;
        int k  = kp * 2;
        float r0 = rs[m*3+0], r1 = rs[m*3+1], r2 = rs[m*3+2];
        float v0 = fmaf(r0, w1s[k],   fmaf(r1, w1s[256+k],   fmaf(r2, w1s[512+k],   b1s[k])));
        float v1 = fmaf(r0, w1s[k+1], fmaf(r1, w1s[256+k+1], fmaf(r2, w1s[512+k+1], b1s[k+1])));
        v0 = fmaxf(v0, 0.f);
        v1 = fmaxf(v1, 0.f);
        __half2 hp = __floats2half2_rn(v0, v1);
        float h0f = __half2float(__low2half(hp));
        float h1f = __half2float(__high2half(hp));
        __half2 lp = __floats2half2_rn(v0 - h0f, v1 - h1f);
        uint32_t off = (uint32_t)m * A_STRIDE + (uint32_t)k * 2;
        *(uint32_t*)(smem + OFF_AHI + off) = *(uint32_t*)&hp;
        *(uint32_t*)(smem + OFF_ALO + off) = *(uint32_t*)&lp;
    }
    __syncthreads();     // A done; w1s/b1s/xs dead -> buf1 free

    // ---- per-thread ldmatrix offsets ----
    const int jj = lane >> 3, rr = lane & 7;
    const int mOff  = ((jj & 1) << 3) + rr;
    const int kOffA = ((jj >> 1) << 3) * 2;          // 0 or 16 B
    const uint32_t aoffA = (uint32_t)(m0w + mOff) * A_STRIDE + kOffA;
    const int nOffB = ((jj >> 1) << 3) + rr;
    const int kOffB = ((jj & 1) << 3) * 2;           // 0 or 16 B
    const uint32_t boffB = (uint32_t)(n0w + nOffB) * B_STRIDE + kOffB;

    // ---- accumulators ----
    float acc[2][8][4];
    #pragma unroll
    for (int mt = 0; mt < 2; mt++)
        #pragma unroll
        for (int nt = 0; nt < 8; nt++)
            #pragma unroll
            for (int q = 0; q < 4; q++) acc[mt][nt][q] = 0.f;

    // ---- mainloop: 8 chunks of k=32, 2-stage B double buffer ----
    for (int c = 0; c < NCHUNK; c++) {
        const int buf = c & 1;
        CP_WAIT0();              // chunk c arrived
        __syncthreads();         // ...and prior-stage reads retired
        if (c + 1 < NCHUNK)
            issue_b_chunk(sb, ghi, glo, c + 1, buf ^ 1, tid);

        #pragma unroll
        for (int kt = 0; kt < 2; kt++) {     // two k16 sub-steps
            uint32_t ah[2][4], al[2][4];
            const uint32_t ka = aoffA + (uint32_t)(c * 32 + kt * 16) * 2;
            LDSM4(ah[0], sb + OFF_AHI + ka);
            LDSM4(ah[1], sb + OFF_AHI + ka + 16 * A_STRIDE);
            LDSM4(al[0], sb + OFF_ALO + ka);
            LDSM4(al[1], sb + OFF_ALO + ka + 16 * A_STRIDE);

            const uint32_t bb = sb + OFF_B0 + (buf * 2) * B_MAT + boffB + kt * 32;
            #pragma unroll
            for (int h = 0; h < 2; h++) {
                uint32_t bh[8], bl[8];
                LDSM4(bh,     bb + (h * 4 + 0) * (8 * B_STRIDE));
                LDSM4(bh + 4, bb + (h * 4 + 2) * (8 * B_STRIDE));
                LDSM4(bl,     bb + B_MAT + (h * 4 + 0) * (8 * B_STRIDE));
                LDSM4(bl + 4, bb + B_MAT + (h * 4 + 2) * (8 * B_STRIDE));
                #pragma unroll
                for (int mt = 0; mt < 2; mt++)
                    #pragma unroll
                    for (int q = 0; q < 4; q++)
                        MMA_F16(acc[mt][h * 4 + q], ah[mt], bh[2 * q], bh[2 * q + 1]);
                #pragma unroll
                for (int mt = 0; mt < 2; mt++)
                    #pragma unroll
                    for (int q = 0; q < 4; q++)
                        MMA_F16(acc[mt][h * 4 + q], al[mt], bh[2 * q], bh[2 * q + 1]);
                #pragma unroll
                for (int mt = 0; mt < 2; mt++)
                    #pragma unroll
                    for (int q = 0; q < 4; q++)
                        MMA_F16(acc[mt][h * 4 + q], ah[mt], bl[2 * q], bl[2 * q + 1]);
            }
        }
    }

    // ---- epilogue: bias2 + relu + layer3 partials ----
    __syncthreads();
    float* psum = (float*)(smem + OFF_PSUM);   // [4 wx][128 row][3]
    #pragma unroll
    for (int mt = 0; mt < 2; mt++) {
        float p[2][3];
        p[0][0]=p[0][1]=p[0][2]=0.f;
        p[1][0]=p[1][1]=p[1][2]=0.f;
        #pragma unroll
        for (int nt = 0; nt < 8; nt++) {
            int n  = n0w + nt * 8 + 2 * t;
            int n2 = n + 1;
            float bn = b2s[n], bn2 = b2s[n2];
            float h00 = fmaxf(acc[mt][nt][0] + bn,  0.f);
            float h01 = fmaxf(acc[mt][nt][1] + bn2, 0.f);
            float h10 = fmaxf(acc[mt][nt][2] + bn,  0.f);
            float h11 = fmaxf(acc[mt][nt][3] + bn2, 0.f);
            #pragma unroll
            for (int j = 0; j < 3; j++) {
                float wA = w3s[n * 3 + j], wB = w3s[n2 * 3 + j];
                p[0][j] = fmaf(h00, wA, fmaf(h01, wB, p[0][j]));
                p[1][j] = fmaf(h10, wA, fmaf(h11, wB, p[1][j]));
            }
        }
        #pragma unroll
        for (int s = 0; s < 2; s++)
            #pragma unroll
            for (int j = 0; j < 3; j++) {
                p[s][j] += __shfl_xor_sync(0xffffffffu, p[s][j], 1);
                p[s][j] += __shfl_xor_sync(0xffffffffu, p[s][j], 2);
            }
        if (t == 0) {
            #pragma unroll
            for (int s = 0; s < 2; s++) {
                int rloc = m0w + mt * 16 + g + 8 * s;
                #pragma unroll
                for (int j = 0; j < 3; j++)
                    psum[(wx * TM + rloc) * 3 + j] = p[s][j];
            }
        }
    }
    __syncthreads();

    // ---- final cross-warp reduce + eigen + store ----
    if (tid < TM) {
        int gr = row0 + tid;
        if (gr < B) {
            float w0 = b3s[0], w1 = b3s[1], w2 = b3s[2];
            #pragma unroll
            for (int q = 0; q < 4; q++) {
                w0 += psum[(q * TM + tid) * 3 + 0];
                w1 += psum[(q * TM + tid) * 3 + 1];
                w2 += psum[(q * TM + tid) * 3 + 2];
            }
            float mean = 0.5f * (w0 + w1);
            float dd   = 0.5f * (w0 - w1);
            float rad  = sqrtf(dd * dd + w2 * w2);
            out[(size_t)gr * 2 + 0] = mean - rad;
            out[(size_t)gr * 2 + 1] = mean + rad;
        }
    }
}

extern "C" void kernel_launch(void* const* d_in, const int* in_sizes, int n_in,
                              void* d_out, int out_size)
{
    const float* x  = (const float*)d_in[0];
    const float* W1 = (const float*)d_in[1];
    const float* b1 = (const float*)d_in[2];
    const float* W2 = (const float*)d_in[3];
    const float* b2 = (const float*)d_in[4];
    const float* W3 = (const float*)d_in[5];
    const float* b3 = (const float*)d_in[6];
    float* out = (float*)d_out;

    int B = in_sizes[0] / 9;
    int grid = (B + TM - 1) / TM;

    prep_w2<<<64, 256>>>(W2);

    cudaFuncSetAttribute(nn_adiab_mma,
                         cudaFuncAttributeMaxDynamicSharedMemorySize, SMEM_BYTES);
    nn_adiab_mma<<<grid, NTHREADS, SMEM_BYTES>>>(x, W1, b1, b2, W3, b3, out, B);
}